// round 11
// baseline (speedup 1.0000x reference)
#include <cuda_runtime.h>
#include <cstdint>

// Problem constants
#define Lnum 3
#define Bsz  512
#define Hd   1024
#define TAUn 96
#define Tt   8

#define GRID 128
#define NTH  512

// SMEM layout (byte offsets)
// 3 stages x (A 34816 + B 34816) = 208896 ; gates ALIASED onto stage region
#define STG   69632
#define ST_A(buf) ((buf) * STG)
#define ST_B(buf) ((buf) * STG + 34816)
#define OFF_GATES 0          // alias: gates live in stage region (dead at epilogue)
#define OFF_BIAS  208896     // 1536
#define SMEM_DYN  210432

#define APITCH 68            // floats per staged row (64 data + 4 pad); 68%32==4 -> conflict-free
#define GPITCH 36
#define GSTRIDE (128 * GPITCH)

// Persistent device state (canonical layouts only)
__device__ __align__(16) float g_wT[(size_t)2 * Lnum * 4096 * 1024]; // rounded [Wih; Whh]
__device__ __align__(16) float g_h[(size_t)2 * Lnum * Bsz * Hd];     // ping-pong hidden (rounded)
__device__ __align__(16) float g_c[(size_t)Lnum * Bsz * Hd];         // cell state (canonical)
__device__ __align__(16) float g_y[(size_t)TAUn * Bsz * Hd];         // exact step outputs
__device__ unsigned int g_bar;                                       // ticket barrier

// ---------------------------------------------------------------- helpers
__device__ __forceinline__ uint32_t smem_u32(const void* p) {
    uint32_t a;
    asm("{ .reg .u64 t; cvta.to.shared.u64 t, %1; cvt.u32.u64 %0, t; }" : "=r"(a) : "l"(p));
    return a;
}
__device__ __forceinline__ float tf32r(float x) {
    uint32_t u;
    asm("cvt.rna.tf32.f32 %0, %1;" : "=r"(u) : "f"(x));
    return __uint_as_float(u);
}
__device__ __forceinline__ float4 cvt4(float4 v) {
    v.x = tf32r(v.x); v.y = tf32r(v.y); v.z = tf32r(v.z); v.w = tf32r(v.w);
    return v;
}
__device__ __forceinline__ float sigmoidf_(float x) { return 1.0f / (1.0f + __expf(-x)); }
__device__ __forceinline__ float tanhf_(float x) {
    float e = __expf(2.0f * x);
    return 1.0f - 2.0f / (e + 1.0f);
}

#define CP16(dst32, src) \
    asm volatile("cp.async.cg.shared.global [%0], [%1], 16;" :: "r"(dst32), "l"(src) : "memory")
#define CP_COMMIT()  asm volatile("cp.async.commit_group;" ::: "memory")
#define CP_WAIT1()   asm volatile("cp.async.wait_group 1;" ::: "memory")

__device__ __forceinline__ void mma_tf32(float& d0, float& d1, float& d2, float& d3,
                                         float a0, float a1, float a2, float a3,
                                         float b0, float b1) {
    asm volatile("mma.sync.aligned.m16n8k8.row.col.f32.tf32.tf32.f32 "
                 "{%0,%1,%2,%3}, {%4,%5,%6,%7}, {%8,%9}, {%0,%1,%2,%3};"
                 : "+f"(d0), "+f"(d1), "+f"(d2), "+f"(d3)
                 : "r"(__float_as_uint(a0)), "r"(__float_as_uint(a1)),
                   "r"(__float_as_uint(a2)), "r"(__float_as_uint(a3)),
                   "r"(__float_as_uint(b0)), "r"(__float_as_uint(b1)));
}

__device__ __forceinline__ void grid_sync() {
    __syncthreads();
    if (threadIdx.x == 0) {
        __threadfence();
        unsigned int ticket = atomicAdd(&g_bar, 1u);
        unsigned int target = ticket - (ticket % GRID) + GRID;
        volatile unsigned int* p = &g_bar;
        while ((int)(*p - target) < 0) { }
        __threadfence();
    }
    __syncthreads();
}

// ---------------------------------------------------------------- kernel
__global__ void __launch_bounds__(NTH, 1)
deepar_mma(const float* __restrict__ hidden,
           const float* __restrict__ cell,
           const float* __restrict__ W_ih,
           const float* __restrict__ W_hh,
           const float* __restrict__ b_ih,
           const float* __restrict__ b_hh,
           const float* __restrict__ W1,
           const float* __restrict__ b1,
           const float* __restrict__ W2,
           const float* __restrict__ b2,
           float* __restrict__ out)
{
    extern __shared__ __align__(16) char smb[];
    const uint32_t sb32 = smem_u32(smb);

    const int tid  = threadIdx.x;
    const int w    = tid >> 5;          // 0..15
    const int lane = tid & 31;
    const int wm   = w >> 2;            // 0..3  (M 32-row slice)
    const int wn   = w & 3;             // 0..3  (gate)
    const int g_   = lane >> 2;         // groupID
    const int t_   = lane & 3;          // threadID_in_group
    const int bt = blockIdx.x >> 5;     // 0..3  batch tile (128 rows)
    const int nt = blockIdx.x & 31;     // 0..31 hidden tile (32 cols)
    const int b0 = bt * 128;
    const int j0 = nt * 32;

    float* gatesS = (float*)(smb + OFF_GATES);   // aliased on stage region
    float* biasS  = (float*)(smb + OFF_BIAS);

    // ================= one-time precompute (elementwise only) =================
    {
        const int gt = blockIdx.x * NTH + tid;
        const float4* s1 = (const float4*)W_ih;
        const float4* s2 = (const float4*)W_hh;
        float4* d = (float4*)g_wT;
        const int PER = 3 * 4096 * 256;          // float4 per weight tensor
        for (int v = gt; v < PER; v += GRID * NTH) {
            d[v]       = cvt4(s1[v]);
            d[v + PER] = cvt4(s2[v]);
        }
        const float4* hs = (const float4*)hidden;
        const float4* cs = (const float4*)cell;
        float4* hd = (float4*)g_h;               // ping 0
        float4* cd = (float4*)g_c;
        const int PH = 3 * 512 * 256;
        for (int v = gt; v < PH; v += GRID * NTH) {
            hd[v] = cvt4(hs[v]);
            cd[v] = cs[v];
        }
    }

    // per-CTA bias (exact fp32): biasS[l*128 + g*32 + jj]
    for (int idx = tid; idx < Lnum * 128; idx += NTH) {
        const int l = idx >> 7, r = idx & 127;
        const int gi = l * 4096 + ((r >> 5) << 10) + j0 + (r & 31);
        biasS[idx] = b_ih[gi] + b_hh[gi];
    }

    // cell ownership: thread owns (m = tid>>2, 8 j's) -- state lives in g_c
    const int ml = tid >> 2;            // 0..127
    const int jb8 = (tid & 3) << 3;     // 0,8,16,24
    grid_sync();

    const uint32_t stage0 = sb32;

    // ================= main recurrence =================
    for (int t = 0; t < TAUn; t++) {
        const int p  = t & 1;
        const int np = 1 - p;
        #pragma unroll
        for (int l = 0; l < Lnum; l++) {
            // canonical A sources: [512 rows][1024 cols]
            const float* Xp = (l == 0)
                ? g_h + (((size_t)(p * 3 + 2) * Bsz) << 10)
                : g_h + (((size_t)(np * 3 + (l - 1)) * Bsz) << 10);
            const float* Hp = g_h + (((size_t)(p * 3 + l) * Bsz) << 10);
            const float* Wi = g_wT + ((size_t)l << 22);                      // l*4096*1024
            const float* Wh = g_wT + ((size_t)(3 + l) << 22);

            float acc[2][4][4];
            #pragma unroll
            for (int mt = 0; mt < 2; mt++)
                #pragma unroll
                for (int jb = 0; jb < 4; jb++)
                    #pragma unroll
                    for (int r = 0; r < 4; r++) acc[mt][jb][r] = 0.0f;

// K=64 chunk staging: A 2048 CP16 (32KB, 128 rows x 64k), B 2048 CP16 (32KB).
// cid_ in 0..2047: row_ = cid_>>4 (0..127), k16_ = cid_&15 (16B sub-chunk).
#define ISSUE(c_, buf_) do {                                                   \
            const int cc_ = (c_);                                              \
            const float* Ap_ = (cc_ < 16) ? Xp : Hp;                           \
            const float* Wp_ = (cc_ < 16) ? Wi : Wh;                           \
            const int kc_ = (cc_ & 15) * 64;                                   \
            const uint32_t dA_ = stage0 + ST_A(buf_);                          \
            const uint32_t dB_ = stage0 + ST_B(buf_);                          \
            _Pragma("unroll")                                                  \
            for (int h_ = 0; h_ < 4; h_++) {                                   \
                const int cid_ = tid + h_ * NTH;                               \
                const int row_ = cid_ >> 4, k16_ = cid_ & 15;                  \
                CP16(dA_ + row_ * 272 + k16_ * 16,                             \
                     Ap_ + ((size_t)(b0 + row_) << 10) + kc_ + k16_ * 4);      \
                const int gg_ = row_ >> 5, jj_ = row_ & 31;                    \
                CP16(dB_ + row_ * 272 + k16_ * 16,                             \
                     Wp_ + ((size_t)(gg_ * 1024 + j0 + jj_) << 10) + kc_ + k16_ * 4); \
            } } while (0)

// Fragment gather for one ks step into register buffer fb_.
#define LOADFRAG(fb_, ks_) do {                                                \
            _Pragma("unroll")                                                  \
            for (int mt = 0; mt < 2; mt++) {                                   \
                const float* Ar = As + (wm * 32 + mt * 16) * APITCH + (ks_) * 8; \
                fa[fb_][mt][0] = Ar[g_ * APITCH + t_];                         \
                fa[fb_][mt][1] = Ar[(g_ + 8) * APITCH + t_];                   \
                fa[fb_][mt][2] = Ar[g_ * APITCH + t_ + 4];                     \
                fa[fb_][mt][3] = Ar[(g_ + 8) * APITCH + t_ + 4];               \
            }                                                                  \
            _Pragma("unroll")                                                  \
            for (int jb = 0; jb < 4; jb++) {                                   \
                const float* Br = Bs + (wn * 32 + jb * 8 + g_) * APITCH        \
                                + (ks_) * 8 + t_;                              \
                fb[fb_][jb][0] = Br[0];                                        \
                fb[fb_][jb][1] = Br[4];                                        \
            } } while (0)

            // 3-stage ring, prefetch distance 2, one sync per chunk.
            ISSUE(0, 0); CP_COMMIT();
            ISSUE(1, 1); CP_COMMIT();

            #pragma unroll 1
            for (int s = 0; s < 32; s++) {
                const int buf = s % 3;
                CP_WAIT1();
                __syncthreads();
                // Buffer (s+2)%3 was consumed at iteration s-1; the sync above
                // guarantees all warps finished reading it. Safe to refill.
                if (s + 2 < 32) { ISSUE(s + 2, (s + 2) % 3); }
                CP_COMMIT();   // dummy when nothing issued: keeps wait count exact

                const float* As = (const float*)(smb + ST_A(buf));
                const float* Bs = (const float*)(smb + ST_B(buf));

                // double-buffered fragment pipeline: LDS(ks+1) overlaps MMA(ks)
                float fa[2][2][4], fb[2][4][2];
                LOADFRAG(0, 0);
                #pragma unroll
                for (int ks = 0; ks < 8; ks++) {
                    const int cur = ks & 1;
                    if (ks < 7) LOADFRAG(cur ^ 1, ks + 1);
                    #pragma unroll
                    for (int mt = 0; mt < 2; mt++)
                        #pragma unroll
                        for (int jb = 0; jb < 4; jb++)
                            mma_tf32(acc[mt][jb][0], acc[mt][jb][1],
                                     acc[mt][jb][2], acc[mt][jb][3],
                                     fa[cur][mt][0], fa[cur][mt][1],
                                     fa[cur][mt][2], fa[cur][mt][3],
                                     fb[cur][jb][0], fb[cur][jb][1]);
                }
            }
#undef ISSUE
#undef LOADFRAG

            // ---- epilogue: accums -> smem gate buffer (aliases stage region) ----
            __syncthreads();
            #pragma unroll
            for (int mt = 0; mt < 2; mt++) {
                const int mb2 = wm * 32 + mt * 16 + g_;
                #pragma unroll
                for (int jb = 0; jb < 4; jb++) {
                    const int jc = jb * 8 + (t_ << 1);
                    float* gp = gatesS + wn * GSTRIDE + mb2 * GPITCH + jc;
                    *(float2*)gp = make_float2(acc[mt][jb][0], acc[mt][jb][1]);
                    *(float2*)(gp + 8 * GPITCH) = make_float2(acc[mt][jb][2], acc[mt][jb][3]);
                }
            }
            __syncthreads();

            // ---- LSTM cell (thread owns (ml, jb8..+8); c state in g_c) ----
            float* cptr = g_c + (((size_t)l * Bsz + b0 + ml) << 10) + j0 + jb8;
            float cv[8];
            {
                float4 c0 = *(const float4*)(cptr);
                float4 c1 = *(const float4*)(cptr + 4);
                cv[0] = c0.x; cv[1] = c0.y; cv[2] = c0.z; cv[3] = c0.w;
                cv[4] = c1.x; cv[5] = c1.y; cv[6] = c1.z; cv[7] = c1.w;
            }
            float G[4][8];
            #pragma unroll
            for (int g = 0; g < 4; g++)
                #pragma unroll
                for (int q4 = 0; q4 < 2; q4++) {
                    float4 v = *(const float4*)(gatesS + g * GSTRIDE + ml * GPITCH
                                                + jb8 + q4 * 4);
                    G[g][q4 * 4 + 0] = v.x; G[g][q4 * 4 + 1] = v.y;
                    G[g][q4 * 4 + 2] = v.z; G[g][q4 * 4 + 3] = v.w;
                }
            float hn[8];
            #pragma unroll
            for (int q = 0; q < 8; q++) {
                const int bb = l * 128 + jb8 + q;
                const float gi = sigmoidf_(G[0][q] + biasS[bb]);
                const float gf = sigmoidf_(G[1][q] + biasS[bb + 32]);
                const float gg = tanhf_  (G[2][q] + biasS[bb + 64]);
                const float go = sigmoidf_(G[3][q] + biasS[bb + 96]);
                const float cn = gf * cv[q] + gi * gg;
                cv[q] = cn;
                hn[q] = go * tanhf_(cn);
            }
            {
                *(float4*)(cptr)     = make_float4(cv[0], cv[1], cv[2], cv[3]);
                *(float4*)(cptr + 4) = make_float4(cv[4], cv[5], cv[6], cv[7]);
            }
            if (l == Lnum - 1) {
                float* yb = g_y + (((size_t)t * Bsz + b0 + ml) << 10) + j0 + jb8;
                #pragma unroll
                for (int q4 = 0; q4 < 2; q4++)
                    *(float4*)(yb + q4 * 4) = make_float4(hn[q4*4], hn[q4*4+1],
                                                          hn[q4*4+2], hn[q4*4+3]);
            }
            // rounded h -> canonical g_h[np][l]
            {
                float* hb = g_h + (((size_t)(np * 3 + l) * Bsz + b0 + ml) << 10)
                          + j0 + jb8;
                #pragma unroll
                for (int q4 = 0; q4 < 2; q4++) {
                    float4 v;
                    v.x = tf32r(hn[q4 * 4 + 0]); v.y = tf32r(hn[q4 * 4 + 1]);
                    v.z = tf32r(hn[q4 * 4 + 2]); v.w = tf32r(hn[q4 * 4 + 3]);
                    *(float4*)(hb + q4 * 4) = v;
                }
            }
            grid_sync();
        }
    }

    // ================= projection =================
    const int gw = blockIdx.x * 16 + w;
    const int OUTHALF = Bsz * TAUn * Tt;
    for (int task = gw; task < TAUn * Bsz; task += GRID * 16) {
        const int t = task / Bsz;
        const int b = task % Bsz;
        const float* y = &g_y[((size_t)t * Bsz + b) << 10];
        float4 yv[8];
        #pragma unroll
        for (int q = 0; q < 8; q++)
            yv[q] = *(const float4*)&y[q * 128 + lane * 4];

        #pragma unroll
        for (int tt = 0; tt < Tt; tt++) {
            float d1 = 0.f, d2 = 0.f;
            #pragma unroll
            for (int q = 0; q < 8; q++) {
                const float4 w1 = *(const float4*)&W1[tt * Hd + q * 128 + lane * 4];
                const float4 w2 = *(const float4*)&W2[tt * Hd + q * 128 + lane * 4];
                d1 += yv[q].x * w1.x + yv[q].y * w1.y + yv[q].z * w1.z + yv[q].w * w1.w;
                d2 += yv[q].x * w2.x + yv[q].y * w2.y + yv[q].z * w2.z + yv[q].w * w2.w;
            }
            #pragma unroll
            for (int offs = 16; offs; offs >>= 1) {
                d1 += __shfl_down_sync(0xffffffffu, d1, offs);
                d2 += __shfl_down_sync(0xffffffffu, d2, offs);
            }
            if (lane == 0) {
                const float mu = d1 + b1[tt];
                const float z = 2.0f * (d2 + b2[tt]);   // BETA = 2
                const float sz = (z > 20.f) ? z : log1pf(__expf(z));
                out[((size_t)b * TAUn + t) * Tt + tt] = mu;
                out[OUTHALF + ((size_t)b * TAUn + t) * Tt + tt] = 0.5f * sz;
            }
        }
    }
}

extern "C" void kernel_launch(void* const* d_in, const int* in_sizes, int n_in,
                              void* d_out, int out_size) {
    (void)in_sizes; (void)n_in; (void)out_size;
    const float* hidden = (const float*)d_in[0];
    const float* cell   = (const float*)d_in[1];
    const float* W_ih   = (const float*)d_in[2];
    const float* W_hh   = (const float*)d_in[3];
    const float* b_ih   = (const float*)d_in[4];
    const float* b_hh   = (const float*)d_in[5];
    const float* W1     = (const float*)d_in[6];
    const float* b1     = (const float*)d_in[7];
    const float* W2     = (const float*)d_in[8];
    const float* b2     = (const float*)d_in[9];
    float* out = (float*)d_out;

    cudaFuncSetAttribute(deepar_mma,
                         cudaFuncAttributeMaxDynamicSharedMemorySize, SMEM_DYN);
    deepar_mma<<<GRID, NTH, SMEM_DYN>>>(hidden, cell, W_ih, W_hh, b_ih, b_hh,
                                        W1, b1, W2, b2, out);
}

// round 13
// speedup vs baseline: 1.1540x; 1.1540x over previous
#include <cuda_runtime.h>
#include <cuda_bf16.h>
#include <cstdint>

// Problem constants
#define Lnum 3
#define Bsz  512
#define Hd   1024
#define TAUn 96
#define Tt   8

#define GRID 128
#define NTH  512

// SMEM layout (byte offsets)
// 3 stages x (A_hi 18432 + A_lo 18432 + B 18432) = 165888 ; gates ALIASED on stages
#define STG   55296
#define ST_AH(buf) ((buf) * STG)
#define ST_AL(buf) ((buf) * STG + 18432)
#define ST_B(buf)  ((buf) * STG + 36864)
#define OFF_GATES 0          // alias: gates (73728B) live in stage region (dead at epilogue)
#define OFF_BIAS  165888     // 1536
#define SMEM_DYN  167424

#define ROWB 144             // staged row pitch bytes (128 data + 16 pad); 36 words %32==4
#define GPITCH 36
#define GSTRIDE (128 * GPITCH)

// Persistent device state
__device__ __align__(16) __nv_bfloat16 g_wT[(size_t)2 * Lnum * 4096 * 1024]; // bf16 [Wih; Whh] 48MB
// hidden: row stride 2048 bf16 -> cols [0,1024) = hi part, [1024,2048) = lo part
__device__ __align__(16) __nv_bfloat16 g_h[(size_t)2 * Lnum * Bsz * 2048];
__device__ __align__(16) float g_c[(size_t)Lnum * Bsz * Hd];                 // cell state fp32
__device__ __align__(16) float g_y[(size_t)TAUn * Bsz * Hd];                 // exact step outputs
__device__ unsigned int g_bar;                                               // ticket barrier

// ---------------------------------------------------------------- helpers
__device__ __forceinline__ uint32_t smem_u32(const void* p) {
    uint32_t a;
    asm("{ .reg .u64 t; cvta.to.shared.u64 t, %1; cvt.u32.u64 %0, t; }" : "=r"(a) : "l"(p));
    return a;
}
__device__ __forceinline__ uint32_t pack_bf2(float x, float y) {
    __nv_bfloat162 h = __floats2bfloat162_rn(x, y);
    return *(uint32_t*)&h;
}
__device__ __forceinline__ float sigmoidf_(float x) { return 1.0f / (1.0f + __expf(-x)); }
__device__ __forceinline__ float tanhf_(float x) {
    float e = __expf(2.0f * x);
    return 1.0f - 2.0f / (e + 1.0f);
}

#define CP16(dst32, src) \
    asm volatile("cp.async.cg.shared.global [%0], [%1], 16;" :: "r"(dst32), "l"(src) : "memory")
#define CP_COMMIT()  asm volatile("cp.async.commit_group;" ::: "memory")
#define CP_WAIT1()   asm volatile("cp.async.wait_group 1;" ::: "memory")

__device__ __forceinline__ void mma_bf16(float& d0, float& d1, float& d2, float& d3,
                                         uint32_t a0, uint32_t a1, uint32_t a2, uint32_t a3,
                                         uint32_t b0, uint32_t b1) {
    asm volatile("mma.sync.aligned.m16n8k16.row.col.f32.bf16.bf16.f32 "
                 "{%0,%1,%2,%3}, {%4,%5,%6,%7}, {%8,%9}, {%0,%1,%2,%3};"
                 : "+f"(d0), "+f"(d1), "+f"(d2), "+f"(d3)
                 : "r"(a0), "r"(a1), "r"(a2), "r"(a3), "r"(b0), "r"(b1));
}

__device__ __forceinline__ void grid_sync() {
    __syncthreads();
    if (threadIdx.x == 0) {
        __threadfence();
        unsigned int ticket = atomicAdd(&g_bar, 1u);
        unsigned int target = ticket - (ticket % GRID) + GRID;
        volatile unsigned int* p = &g_bar;
        while ((int)(*p - target) < 0) { }
        __threadfence();
    }
    __syncthreads();
}

// ---------------------------------------------------------------- kernel
__global__ void __launch_bounds__(NTH, 1)
deepar_mma(const float* __restrict__ hidden,
           const float* __restrict__ cell,
           const float* __restrict__ W_ih,
           const float* __restrict__ W_hh,
           const float* __restrict__ b_ih,
           const float* __restrict__ b_hh,
           const float* __restrict__ W1,
           const float* __restrict__ b1,
           const float* __restrict__ W2,
           const float* __restrict__ b2,
           float* __restrict__ out)
{
    extern __shared__ __align__(16) char smb[];
    const uint32_t sb32 = smem_u32(smb);

    const int tid  = threadIdx.x;
    const int w    = tid >> 5;          // 0..15
    const int lane = tid & 31;
    const int wm   = w >> 2;            // 0..3  (M 32-row slice)
    const int wn   = w & 3;             // 0..3  (gate)
    const int g_   = lane >> 2;         // groupID
    const int t_   = lane & 3;          // threadID_in_group
    const int bt = blockIdx.x >> 5;     // 0..3  batch tile (128 rows)
    const int nt = blockIdx.x & 31;     // 0..31 hidden tile (32 cols)
    const int b0 = bt * 128;
    const int j0 = nt * 32;

    float* gatesS = (float*)(smb + OFF_GATES);   // aliased on stage region
    float* biasS  = (float*)(smb + OFF_BIAS);

    // ================= one-time precompute (elementwise) =================
    {
        const int gt = blockIdx.x * NTH + tid;
        const float4* s1 = (const float4*)W_ih;
        const float4* s2 = (const float4*)W_hh;
        uint2* dw = (uint2*)g_wT;
        const int PER = 3 * 4096 * 256;          // float4 per weight tensor
        for (int v = gt; v < PER; v += GRID * NTH) {
            float4 x = s1[v];
            dw[v] = make_uint2(pack_bf2(x.x, x.y), pack_bf2(x.z, x.w));
            float4 y = s2[v];
            dw[v + PER] = make_uint2(pack_bf2(y.x, y.y), pack_bf2(y.z, y.w));
        }
        // hidden -> hi/lo split, ping 0
        const float4* hs = (const float4*)hidden;
        const float4* cs = (const float4*)cell;
        uint2* hd = (uint2*)g_h;
        float4* cd = (float4*)g_c;
        const int PH = 3 * 512 * 256;
        for (int v = gt; v < PH; v += GRID * NTH) {
            float4 x = hs[v];
            const int lb = v >> 8;               // (l*512 + b)
            const int jq = v & 255;              // j/4
            float hx = __bfloat162float(__float2bfloat16_rn(x.x));
            float hy = __bfloat162float(__float2bfloat16_rn(x.y));
            float hz = __bfloat162float(__float2bfloat16_rn(x.z));
            float hw = __bfloat162float(__float2bfloat16_rn(x.w));
            hd[((size_t)lb << 9) + jq] =
                make_uint2(pack_bf2(hx, hy), pack_bf2(hz, hw));
            hd[((size_t)lb << 9) + 256 + jq] =
                make_uint2(pack_bf2(x.x - hx, x.y - hy), pack_bf2(x.z - hz, x.w - hw));
            cd[v] = cs[v];
        }
    }

    // per-CTA bias (exact fp32): biasS[l*128 + g*32 + jj]
    for (int idx = tid; idx < Lnum * 128; idx += NTH) {
        const int l = idx >> 7, r = idx & 127;
        const int gi = l * 4096 + ((r >> 5) << 10) + j0 + (r & 31);
        biasS[idx] = b_ih[gi] + b_hh[gi];
    }

    // cell ownership: thread owns (m = tid>>2, 8 j's) -- state lives in g_c
    const int ml = tid >> 2;            // 0..127
    const int jb8 = (tid & 3) << 3;     // 0,8,16,24
    grid_sync();

    const uint32_t stage0 = sb32;

    // ================= main recurrence =================
    for (int t = 0; t < TAUn; t++) {
        const int p  = t & 1;
        const int np = 1 - p;
        #pragma unroll
        for (int l = 0; l < Lnum; l++) {
            // A sources (hi/lo rows of 2048): [512 rows][2048]
            const __nv_bfloat16* Xp = (l == 0)
                ? g_h + (((size_t)(p * 3 + 2) * Bsz) << 11)
                : g_h + (((size_t)(np * 3 + (l - 1)) * Bsz) << 11);
            const __nv_bfloat16* Hp = g_h + (((size_t)(p * 3 + l) * Bsz) << 11);
            const __nv_bfloat16* Wi = g_wT + ((size_t)l << 22);
            const __nv_bfloat16* Wh = g_wT + ((size_t)(3 + l) << 22);

            float acc[2][4][4];
            #pragma unroll
            for (int mt = 0; mt < 2; mt++)
                #pragma unroll
                for (int jb = 0; jb < 4; jb++)
                    #pragma unroll
                    for (int r = 0; r < 4; r++) acc[mt][jb][r] = 0.0f;

// K=64 chunk staging (bf16): A hi 1024 + A lo 1024 + B 1024 CP16 (16KB each).
// cid_ in 0..1023: row_ = cid_>>3 (0..127), k16_ = cid_&7 (16B = 8 bf16 sub-chunk).
#define ISSUE(c_, buf_) do {                                                   \
            const int cc_ = (c_);                                              \
            const __nv_bfloat16* Ap_ = (cc_ < 16) ? Xp : Hp;                   \
            const __nv_bfloat16* Wp_ = (cc_ < 16) ? Wi : Wh;                   \
            const int kc_ = (cc_ & 15) * 64;                                   \
            const uint32_t dAH_ = stage0 + ST_AH(buf_);                        \
            const uint32_t dAL_ = stage0 + ST_AL(buf_);                        \
            const uint32_t dB_  = stage0 + ST_B(buf_);                         \
            _Pragma("unroll")                                                  \
            for (int h_ = 0; h_ < 2; h_++) {                                   \
                const int cid_ = tid + h_ * NTH;                               \
                const int row_ = cid_ >> 3, k16_ = cid_ & 7;                   \
                const __nv_bfloat16* asrc_ = Ap_ + ((size_t)(b0 + row_) << 11) \
                                            + kc_ + k16_ * 8;                  \
                CP16(dAH_ + row_ * ROWB + k16_ * 16, asrc_);                   \
                CP16(dAL_ + row_ * ROWB + k16_ * 16, asrc_ + 1024);            \
                const int gg_ = row_ >> 5, jj_ = row_ & 31;                    \
                CP16(dB_ + row_ * ROWB + k16_ * 16,                            \
                     Wp_ + ((size_t)(gg_ * 1024 + j0 + jj_) << 10) + kc_ + k16_ * 8); \
            } } while (0)

// Fragment gather for one k16 step into register buffer fq_.
#define LOADFRAG(fq_, ks_) do {                                                \
            _Pragma("unroll")                                                  \
            for (int mt = 0; mt < 2; mt++) {                                   \
                const char* Ar = Ash + (wm * 32 + mt * 16 + g_) * ROWB         \
                               + (ks_) * 32 + t_ * 4;                          \
                fah[fq_][mt][0] = *(const uint32_t*)(Ar);                      \
                fah[fq_][mt][1] = *(const uint32_t*)(Ar + 8 * ROWB);           \
                fah[fq_][mt][2] = *(const uint32_t*)(Ar + 16);                 \
                fah[fq_][mt][3] = *(const uint32_t*)(Ar + 8 * ROWB + 16);      \
                const char* Al = Ar + 18432;                                   \
                fal[fq_][mt][0] = *(const uint32_t*)(Al);                      \
                fal[fq_][mt][1] = *(const uint32_t*)(Al + 8 * ROWB);           \
                fal[fq_][mt][2] = *(const uint32_t*)(Al + 16);                 \
                fal[fq_][mt][3] = *(const uint32_t*)(Al + 8 * ROWB + 16);      \
            }                                                                  \
            _Pragma("unroll")                                                  \
            for (int jb = 0; jb < 4; jb++) {                                   \
                const char* Br = Bsb + (wn * 32 + jb * 8 + g_) * ROWB          \
                               + (ks_) * 32 + t_ * 4;                          \
                fbr[fq_][jb][0] = *(const uint32_t*)(Br);                      \
                fbr[fq_][jb][1] = *(const uint32_t*)(Br + 16);                 \
            } } while (0)

            // 3-stage ring, prefetch distance 2, one sync per chunk.
            ISSUE(0, 0); CP_COMMIT();
            ISSUE(1, 1); CP_COMMIT();

            #pragma unroll 1
            for (int s = 0; s < 32; s++) {
                const int buf = s % 3;
                CP_WAIT1();
                __syncthreads();
                if (s + 2 < 32) { ISSUE(s + 2, (s + 2) % 3); }
                CP_COMMIT();   // dummy when nothing issued: keeps wait count exact

                const char* Ash = smb + ST_AH(buf);
                const char* Bsb = smb + ST_B(buf);

                // double-buffered fragment pipeline: LDS(ks+1) overlaps MMA(ks)
                uint32_t fah[2][2][4], fal[2][2][4], fbr[2][4][2];
                LOADFRAG(0, 0);
                #pragma unroll
                for (int ks = 0; ks < 4; ks++) {
                    const int cur = ks & 1;
                    if (ks < 3) LOADFRAG(cur ^ 1, ks + 1);
                    #pragma unroll
                    for (int mt = 0; mt < 2; mt++)
                        #pragma unroll
                        for (int jb = 0; jb < 4; jb++) {
                            mma_bf16(acc[mt][jb][0], acc[mt][jb][1],
                                     acc[mt][jb][2], acc[mt][jb][3],
                                     fah[cur][mt][0], fah[cur][mt][1],
                                     fah[cur][mt][2], fah[cur][mt][3],
                                     fbr[cur][jb][0], fbr[cur][jb][1]);
                            mma_bf16(acc[mt][jb][0], acc[mt][jb][1],
                                     acc[mt][jb][2], acc[mt][jb][3],
                                     fal[cur][mt][0], fal[cur][mt][1],
                                     fal[cur][mt][2], fal[cur][mt][3],
                                     fbr[cur][jb][0], fbr[cur][jb][1]);
                        }
                }
            }
#undef ISSUE
#undef LOADFRAG

            // ---- epilogue: accums -> smem gate buffer (aliases stage region) ----
            __syncthreads();
            #pragma unroll
            for (int mt = 0; mt < 2; mt++) {
                const int mb2 = wm * 32 + mt * 16 + g_;
                #pragma unroll
                for (int jb = 0; jb < 4; jb++) {
                    const int jc = jb * 8 + (t_ << 1);
                    float* gp = gatesS + wn * GSTRIDE + mb2 * GPITCH + jc;
                    *(float2*)gp = make_float2(acc[mt][jb][0], acc[mt][jb][1]);
                    *(float2*)(gp + 8 * GPITCH) = make_float2(acc[mt][jb][2], acc[mt][jb][3]);
                }
            }
            __syncthreads();

            // ---- LSTM cell (thread owns (ml, jb8..+8); c state in g_c) ----
            float* cptr = g_c + (((size_t)l * Bsz + b0 + ml) << 10) + j0 + jb8;
            float cv[8];
            {
                float4 c0 = *(const float4*)(cptr);
                float4 c1 = *(const float4*)(cptr + 4);
                cv[0] = c0.x; cv[1] = c0.y; cv[2] = c0.z; cv[3] = c0.w;
                cv[4] = c1.x; cv[5] = c1.y; cv[6] = c1.z; cv[7] = c1.w;
            }
            float G[4][8];
            #pragma unroll
            for (int g = 0; g < 4; g++)
                #pragma unroll
                for (int q4 = 0; q4 < 2; q4++) {
                    float4 v = *(const float4*)(gatesS + g * GSTRIDE + ml * GPITCH
                                                + jb8 + q4 * 4);
                    G[g][q4 * 4 + 0] = v.x; G[g][q4 * 4 + 1] = v.y;
                    G[g][q4 * 4 + 2] = v.z; G[g][q4 * 4 + 3] = v.w;
                }
            float hn[8];
            #pragma unroll
            for (int q = 0; q < 8; q++) {
                const int bb = l * 128 + jb8 + q;
                const float gi = sigmoidf_(G[0][q] + biasS[bb]);
                const float gf = sigmoidf_(G[1][q] + biasS[bb + 32]);
                const float gg = tanhf_  (G[2][q] + biasS[bb + 64]);
                const float go = sigmoidf_(G[3][q] + biasS[bb + 96]);
                const float cn = gf * cv[q] + gi * gg;
                cv[q] = cn;
                hn[q] = go * tanhf_(cn);
            }
            {
                *(float4*)(cptr)     = make_float4(cv[0], cv[1], cv[2], cv[3]);
                *(float4*)(cptr + 4) = make_float4(cv[4], cv[5], cv[6], cv[7]);
            }
            if (l == Lnum - 1) {
                float* yb = g_y + (((size_t)t * Bsz + b0 + ml) << 10) + j0 + jb8;
                #pragma unroll
                for (int q4 = 0; q4 < 2; q4++)
                    *(float4*)(yb + q4 * 4) = make_float4(hn[q4*4], hn[q4*4+1],
                                                          hn[q4*4+2], hn[q4*4+3]);
            }
            // hi/lo bf16 h -> g_h[np][l]  (two 16B stores)
            {
                __nv_bfloat16* hb = g_h
                    + (((size_t)(np * 3 + l) * Bsz + b0 + ml) << 11) + j0 + jb8;
                float hi[8];
                #pragma unroll
                for (int q = 0; q < 8; q++)
                    hi[q] = __bfloat162float(__float2bfloat16_rn(hn[q]));
                uint4 hv;
                hv.x = pack_bf2(hi[0], hi[1]); hv.y = pack_bf2(hi[2], hi[3]);
                hv.z = pack_bf2(hi[4], hi[5]); hv.w = pack_bf2(hi[6], hi[7]);
                *(uint4*)hb = hv;
                uint4 lv;
                lv.x = pack_bf2(hn[0] - hi[0], hn[1] - hi[1]);
                lv.y = pack_bf2(hn[2] - hi[2], hn[3] - hi[3]);
                lv.z = pack_bf2(hn[4] - hi[4], hn[5] - hi[5]);
                lv.w = pack_bf2(hn[6] - hi[6], hn[7] - hi[7]);
                *(uint4*)(hb + 1024) = lv;
            }
            grid_sync();
        }
    }

    // ================= projection =================
    const int gw = blockIdx.x * 16 + w;
    const int OUTHALF = Bsz * TAUn * Tt;
    for (int task = gw; task < TAUn * Bsz; task += GRID * 16) {
        const int t = task / Bsz;
        const int b = task % Bsz;
        const float* y = &g_y[((size_t)t * Bsz + b) << 10];
        float4 yv[8];
        #pragma unroll
        for (int q = 0; q < 8; q++)
            yv[q] = *(const float4*)&y[q * 128 + lane * 4];

        #pragma unroll
        for (int tt = 0; tt < Tt; tt++) {
            float d1 = 0.f, d2 = 0.f;
            #pragma unroll
            for (int q = 0; q < 8; q++) {
                const float4 w1 = *(const float4*)&W1[tt * Hd + q * 128 + lane * 4];
                const float4 w2 = *(const float4*)&W2[tt * Hd + q * 128 + lane * 4];
                d1 += yv[q].x * w1.x + yv[q].y * w1.y + yv[q].z * w1.z + yv[q].w * w1.w;
                d2 += yv[q].x * w2.x + yv[q].y * w2.y + yv[q].z * w2.z + yv[q].w * w2.w;
            }
            #pragma unroll
            for (int offs = 16; offs; offs >>= 1) {
                d1 += __shfl_down_sync(0xffffffffu, d1, offs);
                d2 += __shfl_down_sync(0xffffffffu, d2, offs);
            }
            if (lane == 0) {
                const float mu = d1 + b1[tt];
                const float z = 2.0f * (d2 + b2[tt]);   // BETA = 2
                const float sz = (z > 20.f) ? z : log1pf(__expf(z));
                out[((size_t)b * TAUn + t) * Tt + tt] = mu;
                out[OUTHALF + ((size_t)b * TAUn + t) * Tt + tt] = 0.5f * sz;
            }
        }
    }
}

extern "C" void kernel_launch(void* const* d_in, const int* in_sizes, int n_in,
                              void* d_out, int out_size) {
    (void)in_sizes; (void)n_in; (void)out_size;
    const float* hidden = (const float*)d_in[0];
    const float* cell   = (const float*)d_in[1];
    const float* W_ih   = (const float*)d_in[2];
    const float* W_hh   = (const float*)d_in[3];
    const float* b_ih   = (const float*)d_in[4];
    const float* b_hh   = (const float*)d_in[5];
    const float* W1     = (const float*)d_in[6];
    const float* b1     = (const float*)d_in[7];
    const float* W2     = (const float*)d_in[8];
    const float* b2     = (const float*)d_in[9];
    float* out = (float*)d_out;

    cudaFuncSetAttribute(deepar_mma,
                         cudaFuncAttributeMaxDynamicSharedMemorySize, SMEM_DYN);
    deepar_mma<<<GRID, NTH, SMEM_DYN>>>(hidden, cell, W_ih, W_hh, b_ih, b_hh,
                                        W1, b1, W2, b2, out);
}

// round 14
// speedup vs baseline: 1.7312x; 1.5002x over previous
#include <cuda_runtime.h>
#include <cuda_fp16.h>
#include <cstdint>

// Problem constants
#define Lnum 3
#define Bsz  512
#define Hd   1024
#define TAUn 96
#define Tt   8

#define GRID 128
#define NTH  512

// SMEM layout (byte offsets)
// 3 stages x (A 18432 + B 18432) = 110592 ; gates ALIASED onto stage region
#define STG   36864
#define ST_A(buf) ((buf) * STG)
#define ST_B(buf) ((buf) * STG + 18432)
#define OFF_GATES 0          // alias: gates (73728B) live in stage region (dead at epilogue)
#define OFF_BIAS  110592     // 1536
#define SMEM_DYN  112128

#define ROWB 144             // staged row pitch in bytes (128 data + 16 pad); 36 words %32==4
#define GPITCH 36
#define GSTRIDE (128 * GPITCH)

// Persistent device state
__device__ __align__(16) __half g_wT[(size_t)2 * Lnum * 4096 * 1024]; // fp16 [Wih; Whh] 48MB
__device__ __align__(16) __half g_h[(size_t)2 * Lnum * Bsz * Hd];     // ping-pong hidden fp16
__device__ __align__(16) float g_c[(size_t)Lnum * Bsz * Hd];          // cell state fp32
__device__ __align__(16) float g_y[(size_t)TAUn * Bsz * Hd];          // exact step outputs
__device__ unsigned int g_bar;                                        // ticket barrier

// ---------------------------------------------------------------- helpers
__device__ __forceinline__ uint32_t smem_u32(const void* p) {
    uint32_t a;
    asm("{ .reg .u64 t; cvta.to.shared.u64 t, %1; cvt.u32.u64 %0, t; }" : "=r"(a) : "l"(p));
    return a;
}
__device__ __forceinline__ uint32_t pack_h2(float x, float y) {
    __half2 h = __floats2half2_rn(x, y);
    return *(uint32_t*)&h;
}
__device__ __forceinline__ float sigmoidf_(float x) { return 1.0f / (1.0f + __expf(-x)); }
__device__ __forceinline__ float tanhf_(float x) {
    float e = __expf(2.0f * x);
    return 1.0f - 2.0f / (e + 1.0f);
}

#define CP16(dst32, src) \
    asm volatile("cp.async.cg.shared.global [%0], [%1], 16;" :: "r"(dst32), "l"(src) : "memory")
#define CP_COMMIT()  asm volatile("cp.async.commit_group;" ::: "memory")
#define CP_WAIT1()   asm volatile("cp.async.wait_group 1;" ::: "memory")

__device__ __forceinline__ void mma_f16(float& d0, float& d1, float& d2, float& d3,
                                        uint32_t a0, uint32_t a1, uint32_t a2, uint32_t a3,
                                        uint32_t b0, uint32_t b1) {
    asm volatile("mma.sync.aligned.m16n8k16.row.col.f32.f16.f16.f32 "
                 "{%0,%1,%2,%3}, {%4,%5,%6,%7}, {%8,%9}, {%0,%1,%2,%3};"
                 : "+f"(d0), "+f"(d1), "+f"(d2), "+f"(d3)
                 : "r"(a0), "r"(a1), "r"(a2), "r"(a3), "r"(b0), "r"(b1));
}

__device__ __forceinline__ void grid_sync() {
    __syncthreads();
    if (threadIdx.x == 0) {
        __threadfence();
        unsigned int ticket = atomicAdd(&g_bar, 1u);
        unsigned int target = ticket - (ticket % GRID) + GRID;
        volatile unsigned int* p = &g_bar;
        while ((int)(*p - target) < 0) { }
        __threadfence();
    }
    __syncthreads();
}

// ---------------------------------------------------------------- kernel
__global__ void __launch_bounds__(NTH, 1)
deepar_mma(const float* __restrict__ hidden,
           const float* __restrict__ cell,
           const float* __restrict__ W_ih,
           const float* __restrict__ W_hh,
           const float* __restrict__ b_ih,
           const float* __restrict__ b_hh,
           const float* __restrict__ W1,
           const float* __restrict__ b1,
           const float* __restrict__ W2,
           const float* __restrict__ b2,
           float* __restrict__ out)
{
    extern __shared__ __align__(16) char smb[];
    const uint32_t sb32 = smem_u32(smb);

    const int tid  = threadIdx.x;
    const int w    = tid >> 5;          // 0..15
    const int lane = tid & 31;
    const int wm   = w >> 2;            // 0..3  (M 32-row slice)
    const int wn   = w & 3;             // 0..3  (gate)
    const int g_   = lane >> 2;         // groupID
    const int t_   = lane & 3;          // threadID_in_group
    const int bt = blockIdx.x >> 5;     // 0..3  batch tile (128 rows)
    const int nt = blockIdx.x & 31;     // 0..31 hidden tile (32 cols)
    const int b0 = bt * 128;
    const int j0 = nt * 32;

    float* gatesS = (float*)(smb + OFF_GATES);   // aliased on stage region
    float* biasS  = (float*)(smb + OFF_BIAS);

    // ================= one-time precompute (elementwise, fp16 round) =================
    {
        const int gt = blockIdx.x * NTH + tid;
        const float4* s1 = (const float4*)W_ih;
        const float4* s2 = (const float4*)W_hh;
        uint2* dw = (uint2*)g_wT;
        const int PER = 3 * 4096 * 256;          // float4 per weight tensor
        for (int v = gt; v < PER; v += GRID * NTH) {
            float4 x = s1[v];
            dw[v] = make_uint2(pack_h2(x.x, x.y), pack_h2(x.z, x.w));
            float4 y = s2[v];
            dw[v + PER] = make_uint2(pack_h2(y.x, y.y), pack_h2(y.z, y.w));
        }
        const float4* hs = (const float4*)hidden;
        const float4* cs = (const float4*)cell;
        uint2* hd = (uint2*)g_h;                 // ping 0
        float4* cd = (float4*)g_c;
        const int PH = 3 * 512 * 256;
        for (int v = gt; v < PH; v += GRID * NTH) {
            float4 x = hs[v];
            hd[v] = make_uint2(pack_h2(x.x, x.y), pack_h2(x.z, x.w));
            cd[v] = cs[v];
        }
    }

    // per-CTA bias (exact fp32): biasS[l*128 + g*32 + jj]
    for (int idx = tid; idx < Lnum * 128; idx += NTH) {
        const int l = idx >> 7, r = idx & 127;
        const int gi = l * 4096 + ((r >> 5) << 10) + j0 + (r & 31);
        biasS[idx] = b_ih[gi] + b_hh[gi];
    }

    // cell ownership: thread owns (m = tid>>2, 8 j's) -- state lives in g_c
    const int ml = tid >> 2;            // 0..127
    const int jb8 = (tid & 3) << 3;     // 0,8,16,24
    grid_sync();

    const uint32_t stage0 = sb32;

    // ================= main recurrence =================
    for (int t = 0; t < TAUn; t++) {
        const int p  = t & 1;
        const int np = 1 - p;
        #pragma unroll
        for (int l = 0; l < Lnum; l++) {
            // canonical fp16 A sources: [512 rows][1024 cols]
            const __half* Xp = (l == 0)
                ? g_h + (((size_t)(p * 3 + 2) * Bsz) << 10)
                : g_h + (((size_t)(np * 3 + (l - 1)) * Bsz) << 10);
            const __half* Hp = g_h + (((size_t)(p * 3 + l) * Bsz) << 10);
            const __half* Wi = g_wT + ((size_t)l << 22);
            const __half* Wh = g_wT + ((size_t)(3 + l) << 22);

            float acc[2][4][4];
            #pragma unroll
            for (int mt = 0; mt < 2; mt++)
                #pragma unroll
                for (int jb = 0; jb < 4; jb++)
                    #pragma unroll
                    for (int r = 0; r < 4; r++) acc[mt][jb][r] = 0.0f;

// K=64 chunk staging (fp16): A 1024 CP16 (16KB data, 128 rows x 64k), B 1024 CP16.
// cid_ in 0..1023: row_ = cid_>>3 (0..127), k16_ = cid_&7 (16B = 8 fp16 sub-chunk).
#define ISSUE(c_, buf_) do {                                                   \
            const int cc_ = (c_);                                              \
            const __half* Ap_ = (cc_ < 16) ? Xp : Hp;                          \
            const __half* Wp_ = (cc_ < 16) ? Wi : Wh;                          \
            const int kc_ = (cc_ & 15) * 64;                                   \
            const uint32_t dA_ = stage0 + ST_A(buf_);                          \
            const uint32_t dB_ = stage0 + ST_B(buf_);                          \
            _Pragma("unroll")                                                  \
            for (int h_ = 0; h_ < 2; h_++) {                                   \
                const int cid_ = tid + h_ * NTH;                               \
                const int row_ = cid_ >> 3, k16_ = cid_ & 7;                   \
                CP16(dA_ + row_ * ROWB + k16_ * 16,                            \
                     Ap_ + ((size_t)(b0 + row_) << 10) + kc_ + k16_ * 8);      \
                const int gg_ = row_ >> 5, jj_ = row_ & 31;                    \
                CP16(dB_ + row_ * ROWB + k16_ * 16,                            \
                     Wp_ + ((size_t)(gg_ * 1024 + j0 + jj_) << 10) + kc_ + k16_ * 8); \
            } } while (0)

// Fragment gather for one k16 step into register buffer fq_.
#define LOADFRAG(fq_, ks_) do {                                                \
            _Pragma("unroll")                                                  \
            for (int mt = 0; mt < 2; mt++) {                                   \
                const char* Ar = Asb + (wm * 32 + mt * 16 + g_) * ROWB         \
                               + (ks_) * 32 + t_ * 4;                          \
                fa[fq_][mt][0] = *(const uint32_t*)(Ar);                       \
                fa[fq_][mt][1] = *(const uint32_t*)(Ar + 8 * ROWB);            \
                fa[fq_][mt][2] = *(const uint32_t*)(Ar + 16);                  \
                fa[fq_][mt][3] = *(const uint32_t*)(Ar + 8 * ROWB + 16);       \
            }                                                                  \
            _Pragma("unroll")                                                  \
            for (int jb = 0; jb < 4; jb++) {                                   \
                const char* Br = Bsb + (wn * 32 + jb * 8 + g_) * ROWB          \
                               + (ks_) * 32 + t_ * 4;                          \
                fbr[fq_][jb][0] = *(const uint32_t*)(Br);                      \
                fbr[fq_][jb][1] = *(const uint32_t*)(Br + 16);                 \
            } } while (0)

            // 3-stage ring, prefetch distance 2, one sync per chunk.
            ISSUE(0, 0); CP_COMMIT();
            ISSUE(1, 1); CP_COMMIT();

            #pragma unroll 1
            for (int s = 0; s < 32; s++) {
                const int buf = s % 3;
                CP_WAIT1();
                __syncthreads();
                if (s + 2 < 32) { ISSUE(s + 2, (s + 2) % 3); }
                CP_COMMIT();   // dummy when nothing issued: keeps wait count exact

                const char* Asb = smb + ST_A(buf);
                const char* Bsb = smb + ST_B(buf);

                // double-buffered fragment pipeline: LDS(ks+1) overlaps MMA(ks)
                uint32_t fa[2][2][4], fbr[2][4][2];
                LOADFRAG(0, 0);
                #pragma unroll
                for (int ks = 0; ks < 4; ks++) {
                    const int cur = ks & 1;
                    if (ks < 3) LOADFRAG(cur ^ 1, ks + 1);
                    #pragma unroll
                    for (int mt = 0; mt < 2; mt++)
                        #pragma unroll
                        for (int jb = 0; jb < 4; jb++)
                            mma_f16(acc[mt][jb][0], acc[mt][jb][1],
                                    acc[mt][jb][2], acc[mt][jb][3],
                                    fa[cur][mt][0], fa[cur][mt][1],
                                    fa[cur][mt][2], fa[cur][mt][3],
                                    fbr[cur][jb][0], fbr[cur][jb][1]);
                }
            }
#undef ISSUE
#undef LOADFRAG

            // ---- epilogue: accums -> smem gate buffer (aliases stage region) ----
            __syncthreads();
            #pragma unroll
            for (int mt = 0; mt < 2; mt++) {
                const int mb2 = wm * 32 + mt * 16 + g_;
                #pragma unroll
                for (int jb = 0; jb < 4; jb++) {
                    const int jc = jb * 8 + (t_ << 1);
                    float* gp = gatesS + wn * GSTRIDE + mb2 * GPITCH + jc;
                    *(float2*)gp = make_float2(acc[mt][jb][0], acc[mt][jb][1]);
                    *(float2*)(gp + 8 * GPITCH) = make_float2(acc[mt][jb][2], acc[mt][jb][3]);
                }
            }
            __syncthreads();

            // ---- LSTM cell (thread owns (ml, jb8..+8); c state in g_c) ----
            float* cptr = g_c + (((size_t)l * Bsz + b0 + ml) << 10) + j0 + jb8;
            float cv[8];
            {
                float4 c0 = *(const float4*)(cptr);
                float4 c1 = *(const float4*)(cptr + 4);
                cv[0] = c0.x; cv[1] = c0.y; cv[2] = c0.z; cv[3] = c0.w;
                cv[4] = c1.x; cv[5] = c1.y; cv[6] = c1.z; cv[7] = c1.w;
            }
            float G[4][8];
            #pragma unroll
            for (int g = 0; g < 4; g++)
                #pragma unroll
                for (int q4 = 0; q4 < 2; q4++) {
                    float4 v = *(const float4*)(gatesS + g * GSTRIDE + ml * GPITCH
                                                + jb8 + q4 * 4);
                    G[g][q4 * 4 + 0] = v.x; G[g][q4 * 4 + 1] = v.y;
                    G[g][q4 * 4 + 2] = v.z; G[g][q4 * 4 + 3] = v.w;
                }
            float hn[8];
            #pragma unroll
            for (int q = 0; q < 8; q++) {
                const int bb = l * 128 + jb8 + q;
                const float gi = sigmoidf_(G[0][q] + biasS[bb]);
                const float gf = sigmoidf_(G[1][q] + biasS[bb + 32]);
                const float gg = tanhf_  (G[2][q] + biasS[bb + 64]);
                const float go = sigmoidf_(G[3][q] + biasS[bb + 96]);
                const float cn = gf * cv[q] + gi * gg;
                cv[q] = cn;
                hn[q] = go * tanhf_(cn);
            }
            {
                *(float4*)(cptr)     = make_float4(cv[0], cv[1], cv[2], cv[3]);
                *(float4*)(cptr + 4) = make_float4(cv[4], cv[5], cv[6], cv[7]);
            }
            if (l == Lnum - 1) {
                float* yb = g_y + (((size_t)t * Bsz + b0 + ml) << 10) + j0 + jb8;
                #pragma unroll
                for (int q4 = 0; q4 < 2; q4++)
                    *(float4*)(yb + q4 * 4) = make_float4(hn[q4*4], hn[q4*4+1],
                                                          hn[q4*4+2], hn[q4*4+3]);
            }
            // fp16 h -> canonical g_h[np][l]  (8 fp16 = 16B, one STG.128)
            {
                __half* hb = g_h + (((size_t)(np * 3 + l) * Bsz + b0 + ml) << 10)
                           + j0 + jb8;
                uint4 hv;
                hv.x = pack_h2(hn[0], hn[1]); hv.y = pack_h2(hn[2], hn[3]);
                hv.z = pack_h2(hn[4], hn[5]); hv.w = pack_h2(hn[6], hn[7]);
                *(uint4*)hb = hv;
            }
            grid_sync();
        }
    }

    // ================= projection =================
    const int gw = blockIdx.x * 16 + w;
    const int OUTHALF = Bsz * TAUn * Tt;
    for (int task = gw; task < TAUn * Bsz; task += GRID * 16) {
        const int t = task / Bsz;
        const int b = task % Bsz;
        const float* y = &g_y[((size_t)t * Bsz + b) << 10];
        float4 yv[8];
        #pragma unroll
        for (int q = 0; q < 8; q++)
            yv[q] = *(const float4*)&y[q * 128 + lane * 4];

        #pragma unroll
        for (int tt = 0; tt < Tt; tt++) {
            float d1 = 0.f, d2 = 0.f;
            #pragma unroll
            for (int q = 0; q < 8; q++) {
                const float4 w1 = *(const float4*)&W1[tt * Hd + q * 128 + lane * 4];
                const float4 w2 = *(const float4*)&W2[tt * Hd + q * 128 + lane * 4];
                d1 += yv[q].x * w1.x + yv[q].y * w1.y + yv[q].z * w1.z + yv[q].w * w1.w;
                d2 += yv[q].x * w2.x + yv[q].y * w2.y + yv[q].z * w2.z + yv[q].w * w2.w;
            }
            #pragma unroll
            for (int offs = 16; offs; offs >>= 1) {
                d1 += __shfl_down_sync(0xffffffffu, d1, offs);
                d2 += __shfl_down_sync(0xffffffffu, d2, offs);
            }
            if (lane == 0) {
                const float mu = d1 + b1[tt];
                const float z = 2.0f * (d2 + b2[tt]);   // BETA = 2
                const float sz = (z > 20.f) ? z : log1pf(__expf(z));
                out[((size_t)b * TAUn + t) * Tt + tt] = mu;
                out[OUTHALF + ((size_t)b * TAUn + t) * Tt + tt] = 0.5f * sz;
            }
        }
    }
}

extern "C" void kernel_launch(void* const* d_in, const int* in_sizes, int n_in,
                              void* d_out, int out_size) {
    (void)in_sizes; (void)n_in; (void)out_size;
    const float* hidden = (const float*)d_in[0];
    const float* cell   = (const float*)d_in[1];
    const float* W_ih   = (const float*)d_in[2];
    const float* W_hh   = (const float*)d_in[3];
    const float* b_ih   = (const float*)d_in[4];
    const float* b_hh   = (const float*)d_in[5];
    const float* W1     = (const float*)d_in[6];
    const float* b1     = (const float*)d_in[7];
    const float* W2     = (const float*)d_in[8];
    const float* b2     = (const float*)d_in[9];
    float* out = (float*)d_out;

    cudaFuncSetAttribute(deepar_mma,
                         cudaFuncAttributeMaxDynamicSharedMemorySize, SMEM_DYN);
    deepar_mma<<<GRID, NTH, SMEM_DYN>>>(hidden, cell, W_ih, W_hh, b_ih, b_hh,
                                        W1, b1, W2, b2, out);
}

// round 15
// speedup vs baseline: 1.9811x; 1.1443x over previous
#include <cuda_runtime.h>
#include <cuda_fp16.h>
#include <cstdint>

// Problem constants
#define Lnum 3
#define Bsz  512
#define Hd   1024
#define TAUn 96
#define Tt   8

#define GRID 128
#define NTH  512

// SMEM layout (byte offsets)
// 3 stages x (A 18432 + B 18432) = 110592 ; gates ALIASED onto stage region
#define STG   36864
#define ST_A(buf) ((buf) * STG)
#define ST_B(buf) ((buf) * STG + 18432)
#define OFF_GATES 0          // alias: gates (73728B) live in stage region (dead at epilogue)
#define OFF_BIAS  110592     // 1536
#define SMEM_DYN  112128

#define ROWB 144             // staged row pitch in bytes (128 data + 16 pad); 36 words %32==4
#define GPITCH 36
#define GSTRIDE (128 * GPITCH)

// Persistent device state
__device__ __align__(16) __half g_wT[(size_t)2 * Lnum * 4096 * 1024]; // fp16 [Wih; Whh] 48MB
__device__ __align__(16) __half g_h[(size_t)2 * Lnum * Bsz * Hd];     // ping-pong hidden fp16
__device__ __align__(16) float g_c[(size_t)Lnum * Bsz * Hd];          // cell state fp32
__device__ __align__(16) float g_y[(size_t)TAUn * Bsz * Hd];          // exact step outputs
__device__ unsigned int g_bar;                                        // ticket barrier

// ---------------------------------------------------------------- helpers
__device__ __forceinline__ uint32_t smem_u32(const void* p) {
    uint32_t a;
    asm("{ .reg .u64 t; cvta.to.shared.u64 t, %1; cvt.u32.u64 %0, t; }" : "=r"(a) : "l"(p));
    return a;
}
__device__ __forceinline__ uint32_t pack_h2(float x, float y) {
    __half2 h = __floats2half2_rn(x, y);
    return *(uint32_t*)&h;
}
__device__ __forceinline__ float sigmoidf_(float x) { return 1.0f / (1.0f + __expf(-x)); }
__device__ __forceinline__ float tanhf_(float x) {
    float e = __expf(2.0f * x);
    return 1.0f - 2.0f / (e + 1.0f);
}

#define CP16(dst32, src) \
    asm volatile("cp.async.cg.shared.global [%0], [%1], 16;" :: "r"(dst32), "l"(src) : "memory")
#define CP_COMMIT()  asm volatile("cp.async.commit_group;" ::: "memory")
#define CP_WAIT1()   asm volatile("cp.async.wait_group 1;" ::: "memory")

#define LDSM4(r0, r1, r2, r3, addr) \
    asm volatile("ldmatrix.sync.aligned.m8n8.x4.shared.b16 {%0,%1,%2,%3}, [%4];" \
                 : "=r"(r0), "=r"(r1), "=r"(r2), "=r"(r3) : "r"(addr))

__device__ __forceinline__ void mma_f16(float& d0, float& d1, float& d2, float& d3,
                                        uint32_t a0, uint32_t a1, uint32_t a2, uint32_t a3,
                                        uint32_t b0, uint32_t b1) {
    asm volatile("mma.sync.aligned.m16n8k16.row.col.f32.f16.f16.f32 "
                 "{%0,%1,%2,%3}, {%4,%5,%6,%7}, {%8,%9}, {%0,%1,%2,%3};"
                 : "+f"(d0), "+f"(d1), "+f"(d2), "+f"(d3)
                 : "r"(a0), "r"(a1), "r"(a2), "r"(a3), "r"(b0), "r"(b1));
}

__device__ __forceinline__ void grid_sync() {
    __syncthreads();
    if (threadIdx.x == 0) {
        __threadfence();
        unsigned int ticket = atomicAdd(&g_bar, 1u);
        unsigned int target = ticket - (ticket % GRID) + GRID;
        volatile unsigned int* p = &g_bar;
        while ((int)(*p - target) < 0) { }
        __threadfence();
    }
    __syncthreads();
}

// ---------------------------------------------------------------- kernel
__global__ void __launch_bounds__(NTH, 1)
deepar_mma(const float* __restrict__ hidden,
           const float* __restrict__ cell,
           const float* __restrict__ W_ih,
           const float* __restrict__ W_hh,
           const float* __restrict__ b_ih,
           const float* __restrict__ b_hh,
           const float* __restrict__ W1,
           const float* __restrict__ b1,
           const float* __restrict__ W2,
           const float* __restrict__ b2,
           float* __restrict__ out)
{
    extern __shared__ __align__(16) char smb[];
    const uint32_t sb32 = smem_u32(smb);

    const int tid  = threadIdx.x;
    const int w    = tid >> 5;          // 0..15
    const int lane = tid & 31;
    const int wm   = w >> 2;            // 0..3  (M 32-row slice)
    const int wn   = w & 3;             // 0..3  (gate)
    const int g_   = lane >> 2;         // groupID
    const int t_   = lane & 3;          // threadID_in_group
    const int bt = blockIdx.x >> 5;     // 0..3  batch tile (128 rows)
    const int nt = blockIdx.x & 31;     // 0..31 hidden tile (32 cols)
    const int b0 = bt * 128;
    const int j0 = nt * 32;

    float* gatesS = (float*)(smb + OFF_GATES);   // aliased on stage region
    float* biasS  = (float*)(smb + OFF_BIAS);

    // ldmatrix per-lane base addresses (within stage 0; add buf*STG + ks*32)
    // A x4 (per mt): matrices rows0-7/k0, rows8-15/k0, rows0-7/+16B, rows8-15/+16B
    const uint32_t aAddr0 = sb32 + (wm * 32 + (lane & 15)) * ROWB + ((lane >> 4) << 4);
    const uint32_t aAddr1 = aAddr0 + 16 * ROWB;                   // mt = 1
    // B x4 (per jb pair jp): rows jb*8+0..7 (+0/+16B), rows jb*8+8..15 (+0/+16B)
    const uint32_t bBase = sb32 + 18432
        + (wn * 32 + (lane & 7) + ((lane & 16) ? 8 : 0)) * ROWB
        + ((lane & 8) ? 16 : 0);
    const uint32_t bAddr0 = bBase;                                 // jp = 0 (jb 0,1)
    const uint32_t bAddr1 = bBase + 16 * ROWB;                     // jp = 1 (jb 2,3)

    // ================= one-time precompute (elementwise, fp16 round) =================
    {
        const int gt = blockIdx.x * NTH + tid;
        const float4* s1 = (const float4*)W_ih;
        const float4* s2 = (const float4*)W_hh;
        uint2* dw = (uint2*)g_wT;
        const int PER = 3 * 4096 * 256;          // float4 per weight tensor
        for (int v = gt; v < PER; v += GRID * NTH) {
            float4 x = s1[v];
            dw[v] = make_uint2(pack_h2(x.x, x.y), pack_h2(x.z, x.w));
            float4 y = s2[v];
            dw[v + PER] = make_uint2(pack_h2(y.x, y.y), pack_h2(y.z, y.w));
        }
        const float4* hs = (const float4*)hidden;
        const float4* cs = (const float4*)cell;
        uint2* hd = (uint2*)g_h;                 // ping 0
        float4* cd = (float4*)g_c;
        const int PH = 3 * 512 * 256;
        for (int v = gt; v < PH; v += GRID * NTH) {
            float4 x = hs[v];
            hd[v] = make_uint2(pack_h2(x.x, x.y), pack_h2(x.z, x.w));
            cd[v] = cs[v];
        }
    }

    // per-CTA bias (exact fp32): biasS[l*128 + g*32 + jj]
    for (int idx = tid; idx < Lnum * 128; idx += NTH) {
        const int l = idx >> 7, r = idx & 127;
        const int gi = l * 4096 + ((r >> 5) << 10) + j0 + (r & 31);
        biasS[idx] = b_ih[gi] + b_hh[gi];
    }

    // cell ownership: thread owns (m = tid>>2, 8 j's) -- state lives in g_c
    const int ml = tid >> 2;            // 0..127
    const int jb8 = (tid & 3) << 3;     // 0,8,16,24
    grid_sync();

    const uint32_t stage0 = sb32;

    // ================= main recurrence =================
    for (int t = 0; t < TAUn; t++) {
        const int p  = t & 1;
        const int np = 1 - p;
        #pragma unroll
        for (int l = 0; l < Lnum; l++) {
            // canonical fp16 A sources: [512 rows][1024 cols]
            const __half* Xp = (l == 0)
                ? g_h + (((size_t)(p * 3 + 2) * Bsz) << 10)
                : g_h + (((size_t)(np * 3 + (l - 1)) * Bsz) << 10);
            const __half* Hp = g_h + (((size_t)(p * 3 + l) * Bsz) << 10);
            const __half* Wi = g_wT + ((size_t)l << 22);
            const __half* Wh = g_wT + ((size_t)(3 + l) << 22);

            float acc[2][4][4];
            #pragma unroll
            for (int mt = 0; mt < 2; mt++)
                #pragma unroll
                for (int jb = 0; jb < 4; jb++)
                    #pragma unroll
                    for (int r = 0; r < 4; r++) acc[mt][jb][r] = 0.0f;

// K=64 chunk staging (fp16): A 1024 CP16 (16KB data, 128 rows x 64k), B 1024 CP16.
// cid_ in 0..1023: row_ = cid_>>3 (0..127), k16_ = cid_&7 (16B = 8 fp16 sub-chunk).
#define ISSUE(c_, buf_) do {                                                   \
            const int cc_ = (c_);                                              \
            const __half* Ap_ = (cc_ < 16) ? Xp : Hp;                          \
            const __half* Wp_ = (cc_ < 16) ? Wi : Wh;                          \
            const int kc_ = (cc_ & 15) * 64;                                   \
            const uint32_t dA_ = stage0 + ST_A(buf_);                          \
            const uint32_t dB_ = stage0 + ST_B(buf_);                          \
            _Pragma("unroll")                                                  \
            for (int h_ = 0; h_ < 2; h_++) {                                   \
                const int cid_ = tid + h_ * NTH;                               \
                const int row_ = cid_ >> 3, k16_ = cid_ & 7;                   \
                CP16(dA_ + row_ * ROWB + k16_ * 16,                            \
                     Ap_ + ((size_t)(b0 + row_) << 10) + kc_ + k16_ * 8);      \
                const int gg_ = row_ >> 5, jj_ = row_ & 31;                    \
                CP16(dB_ + row_ * ROWB + k16_ * 16,                            \
                     Wp_ + ((size_t)(gg_ * 1024 + j0 + jj_) << 10) + kc_ + k16_ * 8); \
            } } while (0)

// Fragment gather for one k16 step into register buffer fq_ via ldmatrix.
#define LOADFRAG(fq_, ks_) do {                                                \
            const uint32_t ko_ = bufOff + (ks_) * 32;                          \
            LDSM4(fa[fq_][0][0], fa[fq_][0][1], fa[fq_][0][2], fa[fq_][0][3],  \
                  aAddr0 + ko_);                                               \
            LDSM4(fa[fq_][1][0], fa[fq_][1][1], fa[fq_][1][2], fa[fq_][1][3],  \
                  aAddr1 + ko_);                                               \
            LDSM4(fbr[fq_][0][0], fbr[fq_][0][1], fbr[fq_][1][0], fbr[fq_][1][1], \
                  bAddr0 + ko_);                                               \
            LDSM4(fbr[fq_][2][0], fbr[fq_][2][1], fbr[fq_][3][0], fbr[fq_][3][1], \
                  bAddr1 + ko_);                                               \
            } while (0)

            // 3-stage ring, prefetch distance 2, one sync per chunk.
            ISSUE(0, 0); CP_COMMIT();
            ISSUE(1, 1); CP_COMMIT();

            #pragma unroll 1
            for (int s = 0; s < 32; s++) {
                const int buf = s % 3;
                CP_WAIT1();
                __syncthreads();
                if (s + 2 < 32) { ISSUE(s + 2, (s + 2) % 3); }
                CP_COMMIT();   // dummy when nothing issued: keeps wait count exact

                const uint32_t bufOff = buf * STG;

                // double-buffered fragment pipeline: LDSM(ks+1) overlaps MMA(ks)
                uint32_t fa[2][2][4], fbr[2][4][2];
                LOADFRAG(0, 0);
                #pragma unroll
                for (int ks = 0; ks < 4; ks++) {
                    const int cur = ks & 1;
                    if (ks < 3) LOADFRAG(cur ^ 1, ks + 1);
                    #pragma unroll
                    for (int mt = 0; mt < 2; mt++)
                        #pragma unroll
                        for (int jb = 0; jb < 4; jb++)
                            mma_f16(acc[mt][jb][0], acc[mt][jb][1],
                                    acc[mt][jb][2], acc[mt][jb][3],
                                    fa[cur][mt][0], fa[cur][mt][1],
                                    fa[cur][mt][2], fa[cur][mt][3],
                                    fbr[cur][jb][0], fbr[cur][jb][1]);
                }
            }
#undef ISSUE
#undef LOADFRAG

            // ---- epilogue: accums -> smem gate buffer (aliases stage region) ----
            __syncthreads();
            #pragma unroll
            for (int mt = 0; mt < 2; mt++) {
                const int mb2 = wm * 32 + mt * 16 + g_;
                #pragma unroll
                for (int jb = 0; jb < 4; jb++) {
                    const int jc = jb * 8 + (t_ << 1);
                    float* gp = gatesS + wn * GSTRIDE + mb2 * GPITCH + jc;
                    *(float2*)gp = make_float2(acc[mt][jb][0], acc[mt][jb][1]);
                    *(float2*)(gp + 8 * GPITCH) = make_float2(acc[mt][jb][2], acc[mt][jb][3]);
                }
            }
            __syncthreads();

            // ---- LSTM cell (thread owns (ml, jb8..+8); c state in g_c) ----
            float* cptr = g_c + (((size_t)l * Bsz + b0 + ml) << 10) + j0 + jb8;
            float cv[8];
            {
                float4 c0 = *(const float4*)(cptr);
                float4 c1 = *(const float4*)(cptr + 4);
                cv[0] = c0.x; cv[1] = c0.y; cv[2] = c0.z; cv[3] = c0.w;
                cv[4] = c1.x; cv[5] = c1.y; cv[6] = c1.z; cv[7] = c1.w;
            }
            float G[4][8];
            #pragma unroll
            for (int g = 0; g < 4; g++)
                #pragma unroll
                for (int q4 = 0; q4 < 2; q4++) {
                    float4 v = *(const float4*)(gatesS + g * GSTRIDE + ml * GPITCH
                                                + jb8 + q4 * 4);
                    G[g][q4 * 4 + 0] = v.x; G[g][q4 * 4 + 1] = v.y;
                    G[g][q4 * 4 + 2] = v.z; G[g][q4 * 4 + 3] = v.w;
                }
            float hn[8];
            #pragma unroll
            for (int q = 0; q < 8; q++) {
                const int bb = l * 128 + jb8 + q;
                const float gi = sigmoidf_(G[0][q] + biasS[bb]);
                const float gf = sigmoidf_(G[1][q] + biasS[bb + 32]);
                const float gg = tanhf_  (G[2][q] + biasS[bb + 64]);
                const float go = sigmoidf_(G[3][q] + biasS[bb + 96]);
                const float cn = gf * cv[q] + gi * gg;
                cv[q] = cn;
                hn[q] = go * tanhf_(cn);
            }
            {
                *(float4*)(cptr)     = make_float4(cv[0], cv[1], cv[2], cv[3]);
                *(float4*)(cptr + 4) = make_float4(cv[4], cv[5], cv[6], cv[7]);
            }
            if (l == Lnum - 1) {
                float* yb = g_y + (((size_t)t * Bsz + b0 + ml) << 10) + j0 + jb8;
                #pragma unroll
                for (int q4 = 0; q4 < 2; q4++)
                    *(float4*)(yb + q4 * 4) = make_float4(hn[q4*4], hn[q4*4+1],
                                                          hn[q4*4+2], hn[q4*4+3]);
            }
            // fp16 h -> canonical g_h[np][l]  (8 fp16 = 16B, one STG.128)
            {
                __half* hb = g_h + (((size_t)(np * 3 + l) * Bsz + b0 + ml) << 10)
                           + j0 + jb8;
                uint4 hv;
                hv.x = pack_h2(hn[0], hn[1]); hv.y = pack_h2(hn[2], hn[3]);
                hv.z = pack_h2(hn[4], hn[5]); hv.w = pack_h2(hn[6], hn[7]);
                *(uint4*)hb = hv;
            }
            grid_sync();
        }
    }

    // ================= projection =================
    const int gw = blockIdx.x * 16 + w;
    const int OUTHALF = Bsz * TAUn * Tt;
    for (int task = gw; task < TAUn * Bsz; task += GRID * 16) {
        const int t = task / Bsz;
        const int b = task % Bsz;
        const float* y = &g_y[((size_t)t * Bsz + b) << 10];
        float4 yv[8];
        #pragma unroll
        for (int q = 0; q < 8; q++)
            yv[q] = *(const float4*)&y[q * 128 + lane * 4];

        #pragma unroll
        for (int tt = 0; tt < Tt; tt++) {
            float d1 = 0.f, d2 = 0.f;
            #pragma unroll
            for (int q = 0; q < 8; q++) {
                const float4 w1 = *(const float4*)&W1[tt * Hd + q * 128 + lane * 4];
                const float4 w2 = *(const float4*)&W2[tt * Hd + q * 128 + lane * 4];
                d1 += yv[q].x * w1.x + yv[q].y * w1.y + yv[q].z * w1.z + yv[q].w * w1.w;
                d2 += yv[q].x * w2.x + yv[q].y * w2.y + yv[q].z * w2.z + yv[q].w * w2.w;
            }
            #pragma unroll
            for (int offs = 16; offs; offs >>= 1) {
                d1 += __shfl_down_sync(0xffffffffu, d1, offs);
                d2 += __shfl_down_sync(0xffffffffu, d2, offs);
            }
            if (lane == 0) {
                const float mu = d1 + b1[tt];
                const float z = 2.0f * (d2 + b2[tt]);   // BETA = 2
                const float sz = (z > 20.f) ? z : log1pf(__expf(z));
                out[((size_t)b * TAUn + t) * Tt + tt] = mu;
                out[OUTHALF + ((size_t)b * TAUn + t) * Tt + tt] = 0.5f * sz;
            }
        }
    }
}

extern "C" void kernel_launch(void* const* d_in, const int* in_sizes, int n_in,
                              void* d_out, int out_size) {
    (void)in_sizes; (void)n_in; (void)out_size;
    const float* hidden = (const float*)d_in[0];
    const float* cell   = (const float*)d_in[1];
    const float* W_ih   = (const float*)d_in[2];
    const float* W_hh   = (const float*)d_in[3];
    const float* b_ih   = (const float*)d_in[4];
    const float* b_hh   = (const float*)d_in[5];
    const float* W1     = (const float*)d_in[6];
    const float* b1     = (const float*)d_in[7];
    const float* W2     = (const float*)d_in[8];
    const float* b2     = (const float*)d_in[9];
    float* out = (float*)d_out;

    cudaFuncSetAttribute(deepar_mma,
                         cudaFuncAttributeMaxDynamicSharedMemorySize, SMEM_DYN);
    deepar_mma<<<GRID, NTH, SMEM_DYN>>>(hidden, cell, W_ih, W_hh, b_ih, b_hh,
                                        W1, b1, W2, b2, out);
}